// round 17
// baseline (speedup 1.0000x reference)
#include <cuda_runtime.h>
#include <cuda_fp16.h>
#include <stdint.h>

// Problem constants
#define B     1024
#define S     2048
#define R1    20000
#define R2    40000
#define RTOT  (R1 + R2)
#define NPAIR (B / 2)

#define MAIN_THREADS 512
#define NPART 3                    // uniform partitions over concat stream
#define RPP   20000                // reactions per partition
#define EPT   40                   // entries per thread per partition (pad 20480)
#define PART_PAD (EPT * MAIN_THREADS)   // 20480
#define ONE_IDX 2048u              // y slot holding 1.0 (first-order rb target)
#define KPAD  2048u                // pad-entry key (discard slot)
#define SINK  2049                 // redirect target for non-closing RMWs
#define ACC_SLOTS 2052
#define Y_SLOTS 2052
#define CHUNK 8

// ---------------- static device scratch (no runtime allocation) ----------------
__device__ int       g_counts[NPART][S];   // zero-init; scan re-zeroes
__device__ int       g_cur[NPART][S];
// Key-grouped, transposed entry streams. u16x4: ra | rb<<16 | k<<32
// (first-order entries: rb = ONE_IDX). rid no longer needed in the sweep.
__device__ uint64_t  g_et[NPART][PART_PAD];
// Inverse permutation: g_inv[part][rid] = transposed entry slot of that rate.
__device__ int       g_inv[NPART][RPP];

__device__ __forceinline__ int transposeP(int pos) {
    return (pos % EPT) * MAIN_THREADS + pos / EPT;
}
__device__ __forceinline__ uint64_t pack_entry(unsigned ra, unsigned rb,
                                               unsigned k) {
    return (uint64_t)ra | ((uint64_t)rb << 16) | ((uint64_t)k << 32);
}

// ---------------- prep kernels ----------------

__global__ void hist_kernel(const int* __restrict__ inds_1p,
                            const int* __restrict__ inds_2p) {
    int g = blockIdx.x * blockDim.x + threadIdx.x;
    if (g < RTOT) {
        int part = g / RPP;
        int p = (g < R1) ? inds_1p[g] : inds_2p[g - R1];
        atomicAdd(&g_counts[part][p], 1);
    }
}

// One CTA per partition: exclusive scan over its 2048 bins -> running cursors.
// Re-zeroes its counts slice (restores the zero-at-entry invariant).
__global__ void scan_kernel() {
    __shared__ int buf[2][S];
    const int tid  = threadIdx.x;       // 1024 threads, 2 elems each
    const int part = blockIdx.x;
    int* cnt = g_counts[part];
    int* cur = g_cur[part];

    buf[0][tid]        = cnt[tid];
    buf[0][tid + 1024] = cnt[tid + 1024];
    cnt[tid]        = 0;
    cnt[tid + 1024] = 0;
    __syncthreads();

    int src = 0;
    for (int off = 1; off < S; off <<= 1) {
        int i0 = tid, i1 = tid + 1024;
        int v0 = buf[src][i0] + (i0 >= off ? buf[src][i0 - off] : 0);
        int v1 = buf[src][i1] + (i1 >= off ? buf[src][i1 - off] : 0);
        __syncthreads();
        buf[1 - src][i0] = v0;
        buf[1 - src][i1] = v1;
        __syncthreads();
        src ^= 1;
    }
    cur[tid]        = (tid == 0) ? 0 : buf[src][tid - 1];
    cur[tid + 1024] = buf[src][tid + 1023];
}

// Scatter entries into key-grouped transposed slots; record the inverse
// permutation (rid -> slot) for rate staging; write pad entries.
__global__ void scatter_pad_kernel(const int* __restrict__ inds_1r,
                                   const int* __restrict__ inds_1p,
                                   const int* __restrict__ inds_2r,
                                   const int* __restrict__ inds_2p) {
    int g = blockIdx.x * blockDim.x + threadIdx.x;
    if (g < RTOT) {
        int part = g / RPP;
        int rid  = g - part * RPP;
        unsigned ra, rb, p;
        if (g < R1) {
            ra = (unsigned)inds_1r[g]; rb = ONE_IDX; p = (unsigned)inds_1p[g];
        } else {
            int j = g - R1;
            ra = (unsigned)inds_2r[2 * j]; rb = (unsigned)inds_2r[2 * j + 1];
            p = (unsigned)inds_2p[j];
        }
        int pos  = atomicAdd(&g_cur[part][p], 1);
        int tpos = transposeP(pos);
        g_et[part][tpos]  = pack_entry(ra, rb, p);
        g_inv[part][rid]  = tpos;
    } else if (g < RTOT + NPART * (PART_PAD - RPP)) {
        int q    = g - RTOT;
        int part = q / (PART_PAD - RPP);
        int slot = RPP + q % (PART_PAD - RPP);
        // pad: 1.0 * 1.0 * 0.0 (rate slot zeroed in-kernel) -> discard key
        g_et[part][transposeP(slot)] = pack_entry(ONE_IDX, ONE_IDX, KPAD);
    }
}

// ---------------- main kernel ----------------
// TWO batch rows per CTA; y packed __half2 {row0,row1}; fp32 register run
// accumulation (R8's proven close logic: SEL-redirected interior RMW with a
// sink, per-partition boundary runs via spread SMEM atomics after a barrier).
//
// KEY CHANGE vs R8: rates are staged DIRECTLY INTO ENTRY ORDER using the
// prep-computed inverse permutation — staging does coalesced LDG + one
// random STS.32 per rate (latency-tolerant, fully independent loop), and the
// sweep's rate read becomes a conflict-free coalesced LDS.32 at
// slot = u*512+tid. The critical sweep loop thus has only 2 random LDS per
// entry (y[ra], y[rb]) — the configuration measured at ~70us in R15 —
// without R15's 252MB DRAM round-trip.
//
// SMEM: y2h(8.2KB) + acc2(16.4KB) + rbuf_ent(81.9KB) = 106.5KB -> 2 CTAs/SM.

#define SMEM_BYTES (Y_SLOTS * 4 + 2 * ACC_SLOTS * 4 + PART_PAD * 4)

__device__ __forceinline__ void sweep2(
    const uint64_t* __restrict__ ep,      // g_et[part] + tid
    const __half2* __restrict__ y2h,
    const uint32_t* __restrict__ rent,    // rbuf_ent + tid (entry-order rates)
    float* __restrict__ acc2,
    unsigned& firstk, float& f0, float& f1, unsigned& fdone,
    unsigned& lastk, float& l0, float& l1)
{
    uint64_t buf0[CHUNK], buf1[CHUNK];
    #pragma unroll
    for (int u = 0; u < CHUNK; ++u)
        buf0[u] = ep[u * MAIN_THREADS];

    unsigned curk = 0;
    float a0 = 0.f, a1 = 0.f;
    unsigned first_done = 0;
    firstk = SINK; f0 = 0.f; f1 = 0.f;

    #pragma unroll
    for (int c = 0; c < EPT / CHUNK; ++c) {
        uint64_t* cur = (c & 1) ? buf1 : buf0;
        uint64_t* nxt = (c & 1) ? buf0 : buf1;
        if (c + 1 < EPT / CHUNK) {
            const uint64_t* np = ep + (c + 1) * CHUNK * MAIN_THREADS;
            #pragma unroll
            for (int u = 0; u < CHUNK; ++u)
                nxt[u] = np[u * MAIN_THREADS];
        }
        #pragma unroll
        for (int u = 0; u < CHUNK; ++u) {
            uint64_t e  = cur[u];
            unsigned lo = (unsigned)e;
            unsigned ra = lo & 0xFFFFu;
            unsigned rb = lo >> 16;
            unsigned k  = (unsigned)(e >> 32);
            float2 fa = __half22float2(y2h[ra]);             // random LDS.32
            float2 fb = __half22float2(y2h[rb]);             // random/broadcast
            __half2 hr;                                       // coalesced LDS.32
            *(uint32_t*)&hr = rent[(c * CHUNK + u) * MAIN_THREADS];
            float2 fr = __half22float2(hr);
            float v0 = fa.x * fb.x * fr.x;
            float v1 = fa.y * fb.y * fr.y;
            if (c == 0 && u == 0) {
                curk = k; a0 = v0; a1 = v1;                  // prime first run
            } else {
                unsigned diff     = (k != curk) ? 1u : 0u;
                unsigned do_store = diff & first_done;
                float* addr = do_store ? (acc2 + 2 * curk) : (acc2 + 2 * SINK);
                float2 t = *(float2*)addr;                   // unconditional LDS.64
                t.x += a0; t.y += a1;
                *(float2*)addr = t;                          // unconditional STS.64
                unsigned cap = diff & (1u - first_done);
                firstk = cap ? curk : firstk;
                f0     = cap ? a0   : f0;
                f1     = cap ? a1   : f1;
                first_done |= diff;
                a0 = diff ? v0 : (a0 + v0);
                a1 = diff ? v1 : (a1 + v1);
                curk = k;
            }
        }
    }
    fdone = first_done;
    lastk = curk; l0 = a0; l1 = a1;
}

__global__ __launch_bounds__(MAIN_THREADS, 2)
void reaction_main_kernel(const float* __restrict__ y_in,
                          const float* __restrict__ rates_1st,
                          const float* __restrict__ rates_2nd,
                          float* __restrict__ y_out) {
    extern __shared__ char smraw[];
    __half2*  y2h  = (__half2*)smraw;                          // [Y_SLOTS]
    float*    acc2 = (float*)(smraw + Y_SLOTS * 4);            // [2*ACC_SLOTS]
    uint32_t* rent = (uint32_t*)(smraw + Y_SLOTS * 4 + 2 * ACC_SLOTS * 4); // [PART_PAD]

    const int pair = blockIdx.x;
    const int b0 = 2 * pair, b1 = b0 + 1;
    const int tid = threadIdx.x;

    const float* r0_1 = rates_1st + (size_t)b0 * R1;
    const float* r1_1 = rates_1st + (size_t)b1 * R1;
    const float* r0_2 = rates_2nd + (size_t)b0 * R2;
    const float* r1_2 = rates_2nd + (size_t)b1 * R2;

    // Load two y rows -> packed half2; ONE slot; zero accumulator.
    {
        const float4* s0 = (const float4*)(y_in + (size_t)b0 * S);
        const float4* s1 = (const float4*)(y_in + (size_t)b1 * S);
        float4 q0 = s0[tid], q1 = s1[tid];
        __half2 t[4];
        t[0] = __floats2half2_rn(q0.x, q1.x);
        t[1] = __floats2half2_rn(q0.y, q1.y);
        t[2] = __floats2half2_rn(q0.z, q1.z);
        t[3] = __floats2half2_rn(q0.w, q1.w);
        *(uint4*)(y2h + 4 * tid) = *(const uint4*)t;           // STS.128
        if (tid == 0)
            y2h[ONE_IDX] = __floats2half2_rn(1.f, 1.f);
        #pragma unroll
        for (int i = tid; i < 2 * ACC_SLOTS; i += MAIN_THREADS)
            acc2[i] = 0.f;
    }

    #pragma unroll 1
    for (int part = 0; part < NPART; ++part) {
        __syncthreads();   // prior sweep's rent reads + acc stores done

        // ---- stage rates PRE-PERMUTED into entry order ----
        {
            const int gb = part * RPP;
            const int* inv = g_inv[part];
            for (int i = tid; i < RPP / 2; i += MAIN_THREADS) {
                int g = gb + 2 * i;      // concat rid pair (float2 never straddles R1)
                float2 a, b;
                if (g < R1) {
                    a = *(const float2*)(r0_1 + g);
                    b = *(const float2*)(r1_1 + g);
                } else {
                    a = *(const float2*)(r0_2 + (g - R1));
                    b = *(const float2*)(r1_2 + (g - R1));
                }
                int2 sl = *(const int2*)(inv + 2 * i);          // coalesced LDG.64
                __half2 h0 = __floats2half2_rn(a.x, b.x);
                __half2 h1 = __floats2half2_rn(a.y, b.y);
                rent[sl.x] = *(uint32_t*)&h0;                   // random STS.32
                rent[sl.y] = *(uint32_t*)&h1;                   // random STS.32
            }
            // zero the pad slots (their entries read 1*1*0 into discard key)
            if (tid < PART_PAD - RPP)
                rent[transposeP(RPP + tid)] = 0u;
        }
        __syncthreads();

        unsigned firstk, fdone, lastk;
        float f0, f1, l0, l1;
        sweep2(g_et[part] + tid, y2h, rent + tid, acc2,
               firstk, f0, f1, fdone, lastk, l0, l1);

        __syncthreads();   // interior RMWs visible before boundary atomics
        atomicAdd(&acc2[2 * lastk],     l0);
        atomicAdd(&acc2[2 * lastk + 1], l1);
        if (fdone) {
            atomicAdd(&acc2[2 * firstk],     f0);
            atomicAdd(&acc2[2 * firstk + 1], f1);
        }
    }
    __syncthreads();

    // ---- write out both rows ----
    #pragma unroll
    for (int i = tid; i < S; i += MAIN_THREADS) {
        float2 t = *(const float2*)(acc2 + 2 * i);
        y_out[(size_t)b0 * S + i] = t.x;
        y_out[(size_t)b1 * S + i] = t.y;
    }
}

// ---------------- launch ----------------

extern "C" void kernel_launch(void* const* d_in, const int* in_sizes, int n_in,
                              void* d_out, int out_size) {
    const float* y_in      = (const float*)d_in[0];
    const float* rates_1st = (const float*)d_in[1];
    const float* rates_2nd = (const float*)d_in[2];
    const int*   inds_1r   = (const int*)d_in[3];
    const int*   inds_1p   = (const int*)d_in[4];
    const int*   inds_2r   = (const int*)d_in[5];
    const int*   inds_2p   = (const int*)d_in[6];
    float*       y_out     = (float*)d_out;

    cudaFuncSetAttribute(reaction_main_kernel,
                         cudaFuncAttributeMaxDynamicSharedMemorySize,
                         SMEM_BYTES);

    // Entry-stream + inverse-permutation build (every launch; deterministic).
    hist_kernel<<<(RTOT + 255) / 256, 256>>>(inds_1p, inds_2p);
    scan_kernel<<<NPART, 1024>>>();
    int scat_n = RTOT + NPART * (PART_PAD - RPP);
    scatter_pad_kernel<<<(scat_n + 255) / 256, 256>>>(inds_1r, inds_1p, inds_2r, inds_2p);

    // Main pass: one CTA per TWO batch rows
    reaction_main_kernel<<<NPAIR, MAIN_THREADS, SMEM_BYTES>>>(
        y_in, rates_1st, rates_2nd, y_out);
}